// round 1
// baseline (speedup 1.0000x reference)
#include <cuda_runtime.h>
#include <cuda_bf16.h>

// Problem shape (fixed by the dataset):
//   x:      [4, 2048, 2048] fp32  -> M=8192, K=2048 row-major
//   W_orig: [2048, 16, 128] fp32  -> K=2048, N=2048 row-major
//   A:      [2048, 4]       fp32
//   B:      [4, 16, 128]    fp32  -> [4, 2048]
//   out:    [4, 2048, 16, 128] fp32 -> M=8192, N=2048 row-major
// SCALE = ALPHA / RANK = 4.0/4 = 1.0
//
// Strategy: W_eff = W_orig + A @ B (rank-4 update, 17 MFLOP) folded once per
// launch into a __device__ scratch buffer, then a single fp32 SGEMM
// out = x @ W_eff.

#define M_DIM 8192
#define N_DIM 2048
#define K_DIM 2048
#define RANK_ 4

// Scratch weight buffer (device global: allocation-guard safe, 16 MB)
__device__ float g_Weff[K_DIM * N_DIM];

// ---------------------------------------------------------------------------
// Kernel 1: W_eff[c, n] = W[c, n] + sum_r A[c, r] * B[r, n]   (SCALE == 1.0)
// ---------------------------------------------------------------------------
__global__ void build_weff_kernel(const float* __restrict__ W,
                                  const float* __restrict__ A,
                                  const float* __restrict__ Bk) {
    int idx = blockIdx.x * blockDim.x + threadIdx.x;  // 0 .. K*N/4 - 1 (float4)
    int base = idx * 4;
    if (base >= K_DIM * N_DIM) return;
    int c = base >> 11;        // /2048
    int n = base & 2047;       // %2048

    float4 w = *(const float4*)(W + base);
    float a0 = A[c * RANK_ + 0];
    float a1 = A[c * RANK_ + 1];
    float a2 = A[c * RANK_ + 2];
    float a3 = A[c * RANK_ + 3];

    float4 b0 = *(const float4*)(Bk + 0 * N_DIM + n);
    float4 b1 = *(const float4*)(Bk + 1 * N_DIM + n);
    float4 b2 = *(const float4*)(Bk + 2 * N_DIM + n);
    float4 b3 = *(const float4*)(Bk + 3 * N_DIM + n);

    w.x += a0 * b0.x + a1 * b1.x + a2 * b2.x + a3 * b3.x;
    w.y += a0 * b0.y + a1 * b1.y + a2 * b2.y + a3 * b3.y;
    w.z += a0 * b0.z + a1 * b1.z + a2 * b2.z + a3 * b3.z;
    w.w += a0 * b0.w + a1 * b1.w + a2 * b2.w + a3 * b3.w;

    *(float4*)(g_Weff + base) = w;
}

// ---------------------------------------------------------------------------
// Kernel 2: classic 128x128x8 register-blocked SGEMM, 256 threads,
// 8x8 per-thread micro-tile, float4 global loads, transposed A smem tile.
//   C[M,N] = A[M,K] @ B[K,N]  (all row-major)
// ---------------------------------------------------------------------------
#define BM 128
#define BN 128
#define BK 8
#define TM 8
#define TN 8

__global__ __launch_bounds__(256, 2)
void sgemm_128x128(const float* __restrict__ A,
                   const float* __restrict__ B,
                   float* __restrict__ C) {
    __shared__ float As[BK][BM];   // transposed stage: As[k][m]
    __shared__ float Bs[BK][BN];

    const int tid  = threadIdx.x;           // 0..255
    const int brow = blockIdx.y;            // M tile index (0..63)
    const int bcol = blockIdx.x;            // N tile index (0..15)

    // A-tile load mapping: 128 rows x 8 cols = 256 float4 (2 per row)
    const int aRow = tid >> 1;              // 0..127
    const int aCol = (tid & 1) * 4;         // 0 or 4
    // B-tile load mapping: 8 rows x 128 cols = 256 float4 (32 per row)
    const int bRow = tid >> 5;              // 0..7
    const int bCol = (tid & 31) * 4;        // 0..124

    const float* Aptr = A + (size_t)(brow * BM + aRow) * K_DIM + aCol;
    const float* Bptr = B + (size_t)bRow * N_DIM + bcol * BN + bCol;

    // Compute mapping: 16x16 thread grid, each owns TM x TN outputs
    const int tx = tid & 15;                // N direction
    const int ty = tid >> 4;                // M direction

    float acc[TM][TN];
    #pragma unroll
    for (int i = 0; i < TM; i++)
        #pragma unroll
        for (int j = 0; j < TN; j++)
            acc[i][j] = 0.0f;

    float ar[TM], br[TN];

    for (int k0 = 0; k0 < K_DIM; k0 += BK) {
        float4 a4 = *(const float4*)Aptr;
        float4 b4 = *(const float4*)Bptr;

        As[aCol + 0][aRow] = a4.x;
        As[aCol + 1][aRow] = a4.y;
        As[aCol + 2][aRow] = a4.z;
        As[aCol + 3][aRow] = a4.w;
        *(float4*)&Bs[bRow][bCol] = b4;
        __syncthreads();

        #pragma unroll
        for (int kk = 0; kk < BK; kk++) {
            #pragma unroll
            for (int i = 0; i < TM; i++) ar[i] = As[kk][ty * TM + i];
            #pragma unroll
            for (int j = 0; j < TN; j++) br[j] = Bs[kk][tx * TN + j];
            #pragma unroll
            for (int i = 0; i < TM; i++)
                #pragma unroll
                for (int j = 0; j < TN; j++)
                    acc[i][j] = fmaf(ar[i], br[j], acc[i][j]);
        }
        __syncthreads();

        Aptr += BK;
        Bptr += (size_t)BK * N_DIM;
    }

    float* Cptr = C + (size_t)(brow * BM + ty * TM) * N_DIM + bcol * BN + tx * TN;
    #pragma unroll
    for (int i = 0; i < TM; i++) {
        *(float4*)(Cptr + (size_t)i * N_DIM) =
            make_float4(acc[i][0], acc[i][1], acc[i][2], acc[i][3]);
        *(float4*)(Cptr + (size_t)i * N_DIM + 4) =
            make_float4(acc[i][4], acc[i][5], acc[i][6], acc[i][7]);
    }
}

// ---------------------------------------------------------------------------
// Launch
// ---------------------------------------------------------------------------
extern "C" void kernel_launch(void* const* d_in, const int* in_sizes, int n_in,
                              void* d_out, int out_size) {
    const float* x  = (const float*)d_in[0];   // [8192, 2048]
    const float* W  = (const float*)d_in[1];   // [2048, 2048]
    const float* A  = (const float*)d_in[2];   // [2048, 4]
    const float* Bk = (const float*)d_in[3];   // [4, 2048]
    float* out = (float*)d_out;                // [8192, 2048]

    float* weff;
    cudaGetSymbolAddress((void**)&weff, g_Weff);

    // 1) Fold LoRA update into W_eff
    {
        int total4 = (K_DIM * N_DIM) / 4;      // 1,048,576 float4s
        int threads = 256;
        int blocks = (total4 + threads - 1) / threads;
        build_weff_kernel<<<blocks, threads>>>(W, A, Bk);
    }

    // 2) out = x @ W_eff
    {
        dim3 grid(N_DIM / BN, M_DIM / BM);     // (16, 64)
        sgemm_128x128<<<grid, 256>>>(x, weff, out);
    }
}

// round 7
// speedup vs baseline: 3.6470x; 3.6470x over previous
#include <cuda_runtime.h>
#include <cstdint>

// ============================================================================
// LoRA layer as one tf32 GEMM on the mma.sync (HMMA) path — the harness's
// ptxas targets sm_103 (no 'a'), so tcgen05/TMEM PTX is unavailable.
//   out[8192,2048] = x[8192,2048] @ (W + A@B)[2048,2048]
// Pipeline:
//   1) convert_x:   x fp32 -> tf32(RNA) bits               (g_x, [M,K])
//   2) build_weffT: (W + A@B)^T -> tf32(RNA) bits          (g_WT, [N,K])
//   3) gemm: 128x256 CTA tile, BK=32, 512 thr, 4-stage cp.async,
//      ldmatrix + mma.sync.m16n8k8.tf32
// ============================================================================

#define M_DIM 8192
#define N_DIM 2048
#define K_DIM 2048

#define BM 128
#define BN 256
#define BK 32                      // tf32 elems (128 bytes) per row per stage
#define STAGES 4
#define KITERS (K_DIM / BK)        // 64

#define A_STAGE_BYTES (BM * 128)   // 16 KB
#define B_STAGE_BYTES (BN * 128)   // 32 KB
#define STAGE_BYTES (A_STAGE_BYTES + B_STAGE_BYTES)   // 48 KB
#define SMEM_TOTAL (STAGES * STAGE_BYTES)             // 192 KB

__device__ uint32_t g_x[(size_t)M_DIM * K_DIM];    // x as tf32 bits, [M,K]
__device__ uint32_t g_WT[(size_t)N_DIM * K_DIM];   // (W+AB)^T tf32 bits, [N,K]

// ---------------------------------------------------------------------------
// helpers
// ---------------------------------------------------------------------------
__device__ __forceinline__ uint32_t smem_u32(const void* p) {
    uint32_t a;
    asm("{ .reg .u64 t; cvta.to.shared.u64 t, %1; cvt.u32.u64 %0, t; }"
        : "=r"(a) : "l"(p));
    return a;
}
__device__ __forceinline__ uint32_t f2tf32(float f) {
    uint32_t r;
    asm("cvt.rna.tf32.f32 %0, %1;" : "=r"(r) : "f"(f));
    return r;
}
__device__ __forceinline__ void cp_async16(uint32_t s, const void* g) {
    asm volatile("cp.async.cg.shared.global [%0], [%1], 16;"
                 :: "r"(s), "l"(g) : "memory");
}
__device__ __forceinline__ void cp_commit() {
    asm volatile("cp.async.commit_group;" ::: "memory");
}
template <int N> __device__ __forceinline__ void cp_wait() {
    asm volatile("cp.async.wait_group %0;" :: "n"(N) : "memory");
}
__device__ __forceinline__ void ldsm_x4(uint32_t* r, uint32_t addr) {
    asm volatile("ldmatrix.sync.aligned.m8n8.x4.shared.b16 {%0,%1,%2,%3}, [%4];"
                 : "=r"(r[0]), "=r"(r[1]), "=r"(r[2]), "=r"(r[3]) : "r"(addr));
}
__device__ __forceinline__ void ldsm_x2(uint32_t* r, uint32_t addr) {
    asm volatile("ldmatrix.sync.aligned.m8n8.x2.shared.b16 {%0,%1}, [%2];"
                 : "=r"(r[0]), "=r"(r[1]) : "r"(addr));
}
__device__ __forceinline__ void mma_tf32(float* c, const uint32_t* a, const uint32_t* b) {
    asm volatile(
        "mma.sync.aligned.m16n8k8.row.col.f32.tf32.tf32.f32 "
        "{%0,%1,%2,%3}, {%4,%5,%6,%7}, {%8,%9}, {%0,%1,%2,%3};"
        : "+f"(c[0]), "+f"(c[1]), "+f"(c[2]), "+f"(c[3])
        : "r"(a[0]), "r"(a[1]), "r"(a[2]), "r"(a[3]), "r"(b[0]), "r"(b[1]));
}

// ---------------------------------------------------------------------------
// Kernel 1: x fp32 -> tf32(RNA) bits
// ---------------------------------------------------------------------------
__global__ void convert_x_kernel(const float4* __restrict__ x, uint4* __restrict__ gx) {
    int idx = blockIdx.x * blockDim.x + threadIdx.x;
    float4 v = x[idx];
    uint4 o;
    o.x = f2tf32(v.x); o.y = f2tf32(v.y); o.z = f2tf32(v.z); o.w = f2tf32(v.w);
    gx[idx] = o;
}

// ---------------------------------------------------------------------------
// Kernel 2: W_eff^T: out[n*K + c] = tf32( W[c*N + n] + sum_r A[c,r]*B[r,n] )
// ---------------------------------------------------------------------------
__global__ void build_weffT_kernel(const float* __restrict__ W,
                                   const float* __restrict__ A,
                                   const float* __restrict__ Bk,
                                   uint32_t* __restrict__ out) {
    __shared__ float t[32][33];
    int ci = blockIdx.y * 32;
    int ni = blockIdx.x * 32;
    #pragma unroll
    for (int i = 0; i < 4; i++) {
        int c = ci + threadIdx.y + i * 8;
        int n = ni + threadIdx.x;
        float w = W[(size_t)c * N_DIM + n];
        float a0 = A[c * 4 + 0], a1 = A[c * 4 + 1], a2 = A[c * 4 + 2], a3 = A[c * 4 + 3];
        w += a0 * Bk[n] + a1 * Bk[N_DIM + n] + a2 * Bk[2 * N_DIM + n] + a3 * Bk[3 * N_DIM + n];
        t[threadIdx.y + i * 8][threadIdx.x] = w;
    }
    __syncthreads();
    #pragma unroll
    for (int i = 0; i < 4; i++) {
        int n = ni + threadIdx.y + i * 8;
        int c = ci + threadIdx.x;
        out[(size_t)n * K_DIM + c] = f2tf32(t[threadIdx.x][threadIdx.y + i * 8]);
    }
}

// ---------------------------------------------------------------------------
// Kernel 3: tf32 mma.sync GEMM, 128x256 per CTA, 512 threads
//   warp grid 2(M) x 8(N); warp tile 64x32; per warp: 4 m-tiles x 4 n-tiles
// smem row = 32 tf32 = 128B = 8 chunks of 16B, chunk swizzle c ^= (row & 7)
// ---------------------------------------------------------------------------
__global__ __launch_bounds__(512, 1)
void gemm_tf32_mma(const uint32_t* __restrict__ gA,   // [M,K]
                   const uint32_t* __restrict__ gB,   // [N,K]
                   float* __restrict__ C) {
    extern __shared__ char smem[];
    const uint32_t sbase = smem_u32(smem);

    const int tid  = threadIdx.x;
    const int wid  = tid >> 5;
    const int lane = tid & 31;
    const int wm = wid & 1;        // 0..1  (M)
    const int wn = wid >> 1;       // 0..7  (N)

    const int bm = blockIdx.y;     // 0..63
    const int bn = blockIdx.x;     // 0..7

    // ---- cp.async mappings --------------------------------------------------
    // A: 128 rows x 8 chunks = 1024 chunks -> 2 per thread
    const int arow = tid >> 2;                 // 0..127
    const int ac0  = (tid & 3) * 2;            // chunks ac0, ac0+1
    // B: 256 rows x 8 chunks = 2048 chunks -> 4 per thread
    const int brow = tid >> 1;                 // 0..255
    const int bc0  = (tid & 1) * 4;            // chunks bc0..bc0+3

    const uint32_t* gAp = gA + (size_t)(bm * BM + arow) * K_DIM;
    const uint32_t* gBp = gB + (size_t)(bn * BN + brow) * K_DIM;

    auto load_stage = [&](int s) {
        uint32_t st = sbase + (s % STAGES) * STAGE_BYTES;
        uint32_t sa = st + arow * 128;
        uint32_t sb = st + A_STAGE_BYTES + brow * 128;
        const uint32_t* ga = gAp + s * BK;
        const uint32_t* gb = gBp + s * BK;
        #pragma unroll
        for (int j = 0; j < 2; j++) {
            int c = ac0 + j;
            cp_async16(sa + ((c ^ (arow & 7)) << 4), ga + c * 4);
        }
        #pragma unroll
        for (int j = 0; j < 4; j++) {
            int c = bc0 + j;
            cp_async16(sb + ((c ^ (brow & 7)) << 4), gb + c * 4);
        }
    };

    // ---- ldmatrix address bases --------------------------------------------
    // A fragment (m16k8): 4 matrices = rows {0-7,8-15} x chunk {2ks, 2ks+1}
    //   row = wm*64 + mt*16 + (lane&15); chunk-half h = lane>>4
    const int a_r   = wm * 64 + (lane & 15);
    const int a_h   = lane >> 4;          // 0/1
    const int r7    = lane & 7;           // row&7 for both A and B frag rows
    // B fragment (n8k8): 2 matrices = n rows 0-7 x chunk {2ks, 2ks+1}
    //   n = wn*32 + nt*8 + (lane&7); half h2 = (lane>>3)&1
    const int b_r   = wn * 32 + (lane & 7);
    const int b_h   = (lane >> 3) & 1;

    float acc[4][4][4];
    #pragma unroll
    for (int i = 0; i < 4; i++)
        #pragma unroll
        for (int j = 0; j < 4; j++)
            #pragma unroll
            for (int q = 0; q < 4; q++)
                acc[i][j][q] = 0.0f;

    // ---- prologue ----------------------------------------------------------
    #pragma unroll
    for (int s = 0; s < STAGES - 1; s++) { load_stage(s); cp_commit(); }

    // ---- main loop ---------------------------------------------------------
    for (int k = 0; k < KITERS; k++) {
        cp_wait<STAGES - 2>();
        __syncthreads();

        uint32_t st = sbase + (k % STAGES) * STAGE_BYTES;
        uint32_t sa = st + a_r * 128;                       // + mt*16*128
        uint32_t sb = st + A_STAGE_BYTES + b_r * 128;       // + nt*8*128

        #pragma unroll
        for (int ks = 0; ks < 4; ks++) {
            uint32_t afr[4][4];
            uint32_t bfr[4][2];
            const int ca = ((2 * ks + a_h) ^ r7) << 4;
            const int cb = ((2 * ks + b_h) ^ r7) << 4;
            #pragma unroll
            for (int mt = 0; mt < 4; mt++)
                ldsm_x4(afr[mt], sa + mt * (16 * 128) + ca);
            #pragma unroll
            for (int nt = 0; nt < 4; nt++)
                ldsm_x2(bfr[nt], sb + nt * (8 * 128) + cb);
            #pragma unroll
            for (int mt = 0; mt < 4; mt++)
                #pragma unroll
                for (int nt = 0; nt < 4; nt++)
                    mma_tf32(acc[mt][nt], afr[mt], bfr[nt]);
        }

        if (k + STAGES - 1 < KITERS) load_stage(k + STAGES - 1);
        cp_commit();
    }

    // ---- epilogue ----------------------------------------------------------
    // c0,c1 at (row = lane>>2, col = 2*(lane&3)); c2,c3 at row+8
    const int er = lane >> 2;
    const int ec = (lane & 3) * 2;
    #pragma unroll
    for (int mt = 0; mt < 4; mt++) {
        int m0 = bm * BM + wm * 64 + mt * 16 + er;
        #pragma unroll
        for (int nt = 0; nt < 4; nt++) {
            int n0 = bn * BN + wn * 32 + nt * 8 + ec;
            float2 lo = make_float2(acc[mt][nt][0], acc[mt][nt][1]);
            float2 hi = make_float2(acc[mt][nt][2], acc[mt][nt][3]);
            *(float2*)(C + (size_t)m0 * N_DIM + n0) = lo;
            *(float2*)(C + (size_t)(m0 + 8) * N_DIM + n0) = hi;
        }
    }
}

// ---------------------------------------------------------------------------
// Launch
// ---------------------------------------------------------------------------
extern "C" void kernel_launch(void* const* d_in, const int* in_sizes, int n_in,
                              void* d_out, int out_size) {
    const float* x  = (const float*)d_in[0];   // [8192, 2048]
    const float* W  = (const float*)d_in[1];   // [2048, 2048]
    const float* A  = (const float*)d_in[2];   // [2048, 4]
    const float* Bk = (const float*)d_in[3];   // [4, 2048]
    float* out = (float*)d_out;

    uint32_t *gx, *gwt;
    cudaGetSymbolAddress((void**)&gx, g_x);
    cudaGetSymbolAddress((void**)&gwt, g_WT);

    // 1) x -> tf32 bits
    {
        int total4 = (M_DIM * K_DIM) / 4;
        convert_x_kernel<<<total4 / 256, 256>>>((const float4*)x, (uint4*)gx);
    }
    // 2) W_eff^T -> tf32 bits
    {
        dim3 grid(N_DIM / 32, K_DIM / 32);
        dim3 block(32, 8);
        build_weffT_kernel<<<grid, block>>>(W, A, Bk, gwt);
    }
    // 3) GEMM
    {
        static bool attr_set = false;
        if (!attr_set) {
            cudaFuncSetAttribute(gemm_tf32_mma,
                                 cudaFuncAttributeMaxDynamicSharedMemorySize, SMEM_TOTAL);
            attr_set = true;
        }
        dim3 grid(N_DIM / BN, M_DIM / BM);   // (8, 64)
        gemm_tf32_mma<<<grid, 512, SMEM_TOTAL>>>(gx, gwt, out);
    }
}